// round 5
// baseline (speedup 1.0000x reference)
#include <cuda_runtime.h>
#include <cuda_fp16.h>
#include <math.h>

#define B_TOT   131072
#define NN      17
#define H       32
#define EPS     1e-5f
#define D_IN    53
#define WPB     8           // warps per block (pass1)
#define SPW     8           // samples per warp (pass1)

// ---------------- scratch (device globals; no allocation allowed) ------------
__device__ __half gH2h[(size_t)B_TOT * NN * H];   // 142 MB fp16 staging of h2
__device__ float gSum[NN];
__device__ float gSq[NN];
__device__ float gA[NN];     // gamma*rsqrt(var+eps)/17
__device__ float gCbar;      // sum_n (beta - mean*A)/17

// ---------------- packed f32x2 helpers ---------------------------------------
typedef unsigned long long ull;

__device__ __forceinline__ ull pk2(float lo, float hi) {
    ull r; asm("mov.b64 %0,{%1,%2};" : "=l"(r) : "f"(lo), "f"(hi)); return r;
}
__device__ __forceinline__ void upk2(ull v, float& lo, float& hi) {
    asm("mov.b64 {%0,%1},%2;" : "=f"(lo), "=f"(hi) : "l"(v));
}
__device__ __forceinline__ void ffma2(ull& d, ull a, ull b) {
    asm("fma.rn.f32x2 %0,%1,%2,%0;" : "+l"(d) : "l"(a), "l"(b));
}

__device__ __forceinline__ float elu_f(float x) {
    return fmaxf(x, 0.f) + (__expf(fminf(x, 0.f)) - 1.f);
}

// ---------------------------------------------------------------------------
__global__ void zero_stats_kernel() {
    int t = threadIdx.x;
    if (t < NN) { gSum[t] = 0.f; gSq[t] = 0.f; }
}

// ---------------------------------------------------------------------------
// Pass 1: per-sample 2-layer GCN, h2 -> gH2h (fp16), BN stats accumulate.
// One warp per sample; lane = hidden index. adj prefetched one sample ahead.
__global__ __launch_bounds__(256) void pass1_kernel(
    const float* __restrict__ x_str,   // [B,17,1]
    const float* __restrict__ adj,     // [B,17,17]
    const float* __restrict__ W1,      // [1,32]
    const float* __restrict__ b1,      // [32]
    const float* __restrict__ W2,      // [32,32]
    const float* __restrict__ b2)      // [32]
{
    __shared__ float adjS[WPB][NN * 20];   // support matrix, row stride 20
    __shared__ float bufS[WPB][NN * 36];   // agg staging, row stride 36
    __shared__ float dS[WPB][20];
    __shared__ float xS[WPB][20];
    __shared__ float sS[WPB][20];
    __shared__ float blkAcc[2 * NN];

    const int tid  = threadIdx.x;
    const int lane = tid & 31;
    const int w    = tid >> 5;

    if (tid < 2 * NN) blkAcc[tid] = 0.f;
    __syncthreads();

    const float w1l = W1[lane];
    const float b1l = b1[lane];
    const float b2l = b2[lane];

    ull W2p[16];
    #pragma unroll
    for (int j = 0; j < 16; j++)
        W2p[j] = pk2(W2[(2 * j) * H + lane], W2[(2 * j + 1) * H + lane]);

    float sumP[NN], sqP[NN];
    #pragma unroll
    for (int n = 0; n < NN; n++) { sumP[n] = 0.f; sqP[n] = 0.f; }

    float* aS = adjS[w];
    float* bS = bufS[w];
    float* dv = dS[w];
    float* xs = xS[w];
    float* ss = sS[w];

    const long base = ((long)blockIdx.x * WPB + w) * SPW;

    // ---- prefetch registers (single buffer: STS consumes, LDG refills) ----
    float pre[10];
    float prex;
    {
        const float* adjp = adj + base * (NN * NN);
        #pragma unroll
        for (int j = 0; j < 9; j++) pre[j] = adjp[lane + 32 * j];
        pre[9] = (lane == 0) ? adjp[288] : 0.f;
        prex   = (lane < NN) ? x_str[base * NN + lane] : 0.f;
    }

    #pragma unroll 1
    for (int s = 0; s < SPW; s++) {
        const long b = base + s;

        // commit prefetched sample to shared
        #pragma unroll
        for (int j = 0; j < 9; j++) {
            int idx = lane + 32 * j;
            int n = idx / NN, m = idx - n * NN;
            aS[n * 20 + m] = pre[j];
        }
        if (lane == 0) aS[16 * 20 + 16] = pre[9];
        if (lane < NN) xs[lane] = prex;
        __syncwarp();

        // issue next sample's loads (latency hidden behind compute below)
        if (s + 1 < SPW) {
            const float* adjp = adj + (b + 1) * (NN * NN);
            #pragma unroll
            for (int j = 0; j < 9; j++) pre[j] = adjp[lane + 32 * j];
            pre[9] = (lane == 0) ? adjp[288] : 0.f;
            prex   = (lane < NN) ? x_str[(b + 1) * NN + lane] : 0.f;
        }

        // degrees of A_hat = adj + I, d^-1/2
        if (lane < NN) {
            float dg = 1.0f;
            #pragma unroll
            for (int m = 0; m < NN; m++) dg += aS[lane * 20 + m];
            dv[lane] = dg > 0.f ? rsqrtf(dg) : 0.f;
        }
        __syncwarp();

        // support = D^-1/2 (adj+I) D^-1/2 in place
        // NOTE: j<10 so that lane 0, j=9 covers idx 288 (= element [16][16]).
        #pragma unroll
        for (int j = 0; j < 10; j++) {
            int idx = lane + 32 * j;
            if (idx < NN * NN) {
                int n = idx / NN, m = idx - n * NN;
                float v = aS[n * 20 + m] + (n == m ? 1.f : 0.f);
                aS[n * 20 + m] = v * dv[n] * dv[m];
            }
        }
        __syncwarp();

        // s = support @ x
        if (lane < NN) {
            float acc = 0.f;
            #pragma unroll
            for (int m = 0; m < NN; m++) acc += aS[lane * 20 + m] * xs[m];
            ss[lane] = acc;
        }
        __syncwarp();

        // h1[m] for this lane's hidden channel; pack pairs
        float h1[NN];
        #pragma unroll
        for (int m = 0; m < NN; m++) h1[m] = elu_f(ss[m] * w1l + b1l);
        ull h1p[8];
        #pragma unroll
        for (int j = 0; j < 8; j++) h1p[j] = pk2(h1[2 * j], h1[2 * j + 1]);
        const float h1_16 = h1[16];

        // agg = support @ h1 -> bufS   (two independent f32x2 chains)
        #pragma unroll
        for (int n = 0; n < NN; n++) {
            const ulonglong2* av = reinterpret_cast<const ulonglong2*>(&aS[n * 20]);
            ull a0 = 0ull, a1 = 0ull;
            #pragma unroll
            for (int q = 0; q < 4; q++) {
                ulonglong2 v = av[q];
                ffma2(a0, v.x, h1p[2 * q]);
                ffma2(a1, v.y, h1p[2 * q + 1]);
            }
            float l0, hh0, l1, hh1;
            upk2(a0, l0, hh0); upk2(a1, l1, hh1);
            bS[n * 36 + lane] = (l0 + hh0) + (l1 + hh1) + aS[n * 20 + 16] * h1_16;
        }
        __syncwarp();

        // t = agg @ W2 + b2 ; h2 = elu(t) ; fp16 store + stats
        __half* outp = gH2h + b * (NN * H);
        #pragma unroll
        for (int n = 0; n < NN; n++) {
            const ulonglong2* bv = reinterpret_cast<const ulonglong2*>(&bS[n * 36]);
            ull a0 = 0ull, a1 = 0ull;
            #pragma unroll
            for (int q = 0; q < 8; q++) {
                ulonglong2 v = bv[q];
                ffma2(a0, v.x, W2p[2 * q]);
                ffma2(a1, v.y, W2p[2 * q + 1]);
            }
            float l0, hh0, l1, hh1;
            upk2(a0, l0, hh0); upk2(a1, l1, hh1);
            float h2 = elu_f((l0 + hh0) + (l1 + hh1) + b2l);
            outp[n * H + lane] = __float2half(h2);
            sumP[n] += h2;
            sqP[n]  += h2 * h2;
        }
        __syncwarp();
    }

    // warp butterfly reduce stats
    #pragma unroll
    for (int n = 0; n < NN; n++) {
        #pragma unroll
        for (int off = 16; off; off >>= 1) {
            sumP[n] += __shfl_xor_sync(0xffffffffu, sumP[n], off);
            sqP[n]  += __shfl_xor_sync(0xffffffffu, sqP[n],  off);
        }
    }
    if (lane == 0) {
        #pragma unroll
        for (int n = 0; n < NN; n++) {
            atomicAdd(&blkAcc[n], sumP[n]);
            atomicAdd(&blkAcc[NN + n], sqP[n]);
        }
    }
    __syncthreads();
    if (tid < NN)           atomicAdd(&gSum[tid],      blkAcc[tid]);
    else if (tid < 2 * NN)  atomicAdd(&gSq[tid - NN],  blkAcc[tid]);
}

// ---------------------------------------------------------------------------
__global__ void finalize_kernel(const float* __restrict__ gamma,
                                const float* __restrict__ beta)
{
    int n = threadIdx.x;
    float Cl = 0.f;
    if (n < NN) {
        const float inv_cnt = 1.f / ((float)B_TOT * (float)H);
        float mean = gSum[n] * inv_cnt;
        float var  = gSq[n] * inv_cnt - mean * mean;
        float rs   = rsqrtf(var + EPS);
        float A    = gamma[n] * rs;
        float C    = beta[n] - mean * A;
        gA[n] = A * (1.f / 17.f);
        Cl    = C * (1.f / 17.f);
    }
    #pragma unroll
    for (int off = 16; off; off >>= 1) Cl += __shfl_xor_sync(0xffffffffu, Cl, off);
    if (n == 0) gCbar = Cl;
}

// ---------------------------------------------------------------------------
// Pass 2: BN-fold + node mean + MLP head. 128-thread blocks (4 warps).
// Phase A (lane=h): comb[53] per sample -> shared fp32 (stride 53: conflict-free).
// Phase B (lane=sample): layer1 in 4 chunks of 16 outputs fused into layer2 accum.
#define P2_WARPS 4
#define CSTRIDE  53
#define P2_SMEM_FLOATS (3392 + 2048 + P2_WARPS*32*CSTRIDE + 64 + 32 + 32 + 18 + 2)

__global__ __launch_bounds__(128) void pass2_kernel(
    const float* __restrict__ x_raw,   // [B,17]
    const float* __restrict__ x_cov,   // [B,3]
    const float* __restrict__ age,     // [B,1]
    const float* __restrict__ Wr1,     // [53,64]
    const float* __restrict__ br1,     // [64]
    const float* __restrict__ Wr2,     // [64,32]
    const float* __restrict__ br2,     // [32]
    const float* __restrict__ Wr3,     // [32,1]
    const float* __restrict__ br3,     // [1]
    float* __restrict__ out)           // [B,1]
{
    extern __shared__ float sm[];
    float* Wr1s  = sm;                         // 3392 (16B aligned)
    float* Wr2s  = Wr1s + 3392;                // 2048 (16B aligned)
    float* combS = Wr2s + 2048;                // 4*32*53
    float* br1s  = combS + P2_WARPS * 32 * CSTRIDE; // 64 (offset 12224: 16B aligned)
    float* br2s  = br1s + 64;                  // 32
    float* wr3s  = br2s + 32;                  // 32
    float* As_   = wr3s + 32;                  // 18
    float* misc  = As_ + 18;                   // [0]=cbar [1]=br3

    const int tid = threadIdx.x;
    for (int i = tid; i < 3392; i += 128) Wr1s[i] = Wr1[i];
    for (int i = tid; i < 2048; i += 128) Wr2s[i] = Wr2[i];
    if (tid < 64) br1s[tid] = br1[tid];
    if (tid < 32) { br2s[tid] = br2[tid]; wr3s[tid] = Wr3[tid]; }
    if (tid < NN) As_[tid] = gA[tid];
    if (tid == 0) { misc[0] = gCbar; misc[1] = br3[0]; }
    __syncthreads();

    const int lane = tid & 31;
    const int w    = tid >> 5;
    float* comb = combS + w * (32 * CSTRIDE);
    const long base = ((long)blockIdx.x * P2_WARPS + w) * 32;

    float As_r[NN];
    #pragma unroll
    for (int n = 0; n < NN; n++) As_r[n] = As_[n];
    const float cbar = misc[0];

    // ---- Phase A: build comb rows (fp32) for this warp's 32 samples ----
    #pragma unroll 1
    for (int s2 = 0; s2 < 32; s2++) {
        const long b = base + s2;
        const __half* hp = gH2h + b * (NN * H);
        float ge = cbar;
        #pragma unroll
        for (int n = 0; n < NN; n++)
            ge += As_r[n] * __half2float(hp[n * H + lane]);
        comb[s2 * CSTRIDE + lane] = ge;
        if (lane < NN)
            comb[s2 * CSTRIDE + 32 + lane] = x_raw[b * NN + lane];
        else if (lane < 20)
            comb[s2 * CSTRIDE + 32 + lane] = x_cov[b * 3 + (lane - NN)];
        else if (lane == 20)
            comb[s2 * CSTRIDE + 52] = age[b];
    }
    __syncwarp();

    // ---- Phase B: lane = sample; chunked layer1 fused into layer2 ----
    const long b = base + lane;
    const float* cl = comb + lane * CSTRIDE;   // odd stride: conflict-free

    ull z2a[16];
    const ull* b2u = reinterpret_cast<const ull*>(br2s);
    #pragma unroll
    for (int j = 0; j < 16; j++) z2a[j] = b2u[j];

    #pragma unroll
    for (int c = 0; c < 4; c++) {
        // layer1 chunk: outputs [16c, 16c+16)
        ull za[8];
        const ull* b1u = reinterpret_cast<const ull*>(br1s + 16 * c);
        #pragma unroll
        for (int j = 0; j < 8; j++) za[j] = b1u[j];

        #pragma unroll 1
        for (int p = 0; p < 26; p++) {                 // inputs 0..51 in pairs
            float f0 = cl[2 * p];
            float f1 = cl[2 * p + 1];
            ull ca = pk2(f0, f0);
            ull cb = pk2(f1, f1);
            const ulonglong2* wa = reinterpret_cast<const ulonglong2*>(&Wr1s[(2 * p) * 64 + 16 * c]);
            const ulonglong2* wb = reinterpret_cast<const ulonglong2*>(&Wr1s[(2 * p + 1) * 64 + 16 * c]);
            #pragma unroll
            for (int q = 0; q < 4; q++) {
                ulonglong2 va = wa[q];
                ffma2(za[2 * q],     ca, va.x);
                ffma2(za[2 * q + 1], ca, va.y);
            }
            #pragma unroll
            for (int q = 0; q < 4; q++) {
                ulonglong2 vb = wb[q];
                ffma2(za[2 * q],     cb, vb.x);
                ffma2(za[2 * q + 1], cb, vb.y);
            }
        }
        {   // input 52
            float ci = cl[52];
            ull c2 = pk2(ci, ci);
            const ulonglong2* wv = reinterpret_cast<const ulonglong2*>(&Wr1s[52 * 64 + 16 * c]);
            #pragma unroll
            for (int q = 0; q < 4; q++) {
                ulonglong2 v = wv[q];
                ffma2(za[2 * q],     c2, v.x);
                ffma2(za[2 * q + 1], c2, v.y);
            }
        }

        // ReLU chunk, fold into layer2 accumulators
        #pragma unroll
        for (int j = 0; j < 8; j++) {
            float r0, r1; upk2(za[j], r0, r1);
            r0 = fmaxf(r0, 0.f); r1 = fmaxf(r1, 0.f);
            int k0 = 16 * c + 2 * j;
            ull ca = pk2(r0, r0);
            ull cb = pk2(r1, r1);
            const ulonglong2* wa = reinterpret_cast<const ulonglong2*>(&Wr2s[k0 * 32]);
            const ulonglong2* wb = reinterpret_cast<const ulonglong2*>(&Wr2s[(k0 + 1) * 32]);
            #pragma unroll
            for (int q = 0; q < 8; q++) {
                ulonglong2 va = wa[q];
                ffma2(z2a[2 * q],     ca, va.x);
                ffma2(z2a[2 * q + 1], ca, va.y);
            }
            #pragma unroll
            for (int q = 0; q < 8; q++) {
                ulonglong2 vb = wb[q];
                ffma2(z2a[2 * q],     cb, vb.x);
                ffma2(z2a[2 * q + 1], cb, vb.y);
            }
        }
    }

    // layer 3: 32 -> 1
    float acc = misc[1];
    #pragma unroll
    for (int j = 0; j < 16; j++) {
        float lo, hi; upk2(z2a[j], lo, hi);
        acc += fmaxf(lo, 0.f) * wr3s[2 * j];
        acc += fmaxf(hi, 0.f) * wr3s[2 * j + 1];
    }
    out[b] = 1.f / (1.f + __expf(-acc));
}

// ---------------------------------------------------------------------------
extern "C" void kernel_launch(void* const* d_in, const int* in_sizes, int n_in,
                              void* d_out, int out_size)
{
    const float* x_str = (const float*)d_in[0];
    const float* x_raw = (const float*)d_in[1];
    const float* adj   = (const float*)d_in[2];
    const float* x_cov = (const float*)d_in[3];
    const float* age   = (const float*)d_in[4];
    const float* W1    = (const float*)d_in[5];
    const float* b1    = (const float*)d_in[6];
    const float* W2    = (const float*)d_in[7];
    const float* b2    = (const float*)d_in[8];
    const float* gamma = (const float*)d_in[9];
    const float* beta  = (const float*)d_in[10];
    const float* Wr1   = (const float*)d_in[11];
    const float* br1   = (const float*)d_in[12];
    const float* Wr2   = (const float*)d_in[13];
    const float* br2   = (const float*)d_in[14];
    const float* Wr3   = (const float*)d_in[15];
    const float* br3   = (const float*)d_in[16];

    const int blocks1 = B_TOT / (WPB * SPW);          // 2048
    const int blocks2 = B_TOT / (P2_WARPS * 32);      // 1024
    const int smem2   = P2_SMEM_FLOATS * 4;           // ~49.5 KB

    static int attr_done = 0;
    if (!attr_done) {
        cudaFuncSetAttribute(pass2_kernel,
                             cudaFuncAttributeMaxDynamicSharedMemorySize, smem2);
        attr_done = 1;
    }

    zero_stats_kernel<<<1, 32>>>();
    pass1_kernel<<<blocks1, 256>>>(x_str, adj, W1, b1, W2, b2);
    finalize_kernel<<<1, 32>>>(gamma, beta);
    pass2_kernel<<<blocks2, 128, smem2>>>(x_raw, x_cov, age,
                                          Wr1, br1, Wr2, br2, Wr3, br3,
                                          (float*)d_out);
}

// round 6
// speedup vs baseline: 1.1814x; 1.1814x over previous
#include <cuda_runtime.h>
#include <cuda_fp16.h>
#include <math.h>

#define B_TOT   131072
#define NN      17
#define H       32
#define EPS     1e-5f
#define D_IN    53
#define WPB     8           // warps per block (pass1)
#define SPW     8           // samples per warp (pass1)

// ---------------- scratch (device globals; no allocation allowed) ------------
__device__ __half gH2h[(size_t)B_TOT * NN * H];   // 142 MB fp16 staging of h2
__device__ float gSum[NN];
__device__ float gSq[NN];
__device__ float gA[NN];     // gamma*rsqrt(var+eps)/17
__device__ float gCbar;      // sum_n (beta - mean*A)/17

// ---------------- packed f32x2 helpers ---------------------------------------
typedef unsigned long long ull;

__device__ __forceinline__ ull pk2(float lo, float hi) {
    ull r; asm("mov.b64 %0,{%1,%2};" : "=l"(r) : "f"(lo), "f"(hi)); return r;
}
__device__ __forceinline__ void upk2(ull v, float& lo, float& hi) {
    asm("mov.b64 {%0,%1},%2;" : "=f"(lo), "=f"(hi) : "l"(v));
}
__device__ __forceinline__ void ffma2(ull& d, ull a, ull b) {
    asm("fma.rn.f32x2 %0,%1,%2,%0;" : "+l"(d) : "l"(a), "l"(b));
}

__device__ __forceinline__ float elu_f(float x) {
    return fmaxf(x, 0.f) + (__expf(fminf(x, 0.f)) - 1.f);
}

// ---------------- cp.async helpers -------------------------------------------
__device__ __forceinline__ void cp_async4(unsigned dst, const float* src) {
    asm volatile("cp.async.ca.shared.global [%0], [%1], 4;" :: "r"(dst), "l"(src));
}
__device__ __forceinline__ void cp_commit() {
    asm volatile("cp.async.commit_group;" ::: "memory");
}
__device__ __forceinline__ void cp_wait0() {
    asm volatile("cp.async.wait_group 0;" ::: "memory");
}

// ---------------------------------------------------------------------------
__global__ void zero_stats_kernel() {
    int t = threadIdx.x;
    if (t < NN) { gSum[t] = 0.f; gSq[t] = 0.f; }
}

// ---------------------------------------------------------------------------
// Pass 1: per-sample 2-layer GCN, h2 -> gH2h (fp16), BN stats accumulate.
// One warp per sample; lane = hidden index. adj double-buffered via cp.async,
// scattered directly into padded stride-20 layout. D^{-1/2} folded into
// operands (no in-place support build).
__global__ __launch_bounds__(256, 2) void pass1_kernel(
    const float* __restrict__ x_str,   // [B,17,1]
    const float* __restrict__ adj,     // [B,17,17]
    const float* __restrict__ W1,      // [1,32]
    const float* __restrict__ b1,      // [32]
    const float* __restrict__ W2,      // [32,32]
    const float* __restrict__ b2)      // [32]
{
    __shared__ float adjS[WPB][2][NN * 20];   // raw adj, padded rows, 2 buffers
    __shared__ float xS[WPB][2][20];
    __shared__ float bufS[WPB][NN * 36];      // agg staging, row stride 36
    __shared__ float dS[WPB][20];             // dv
    __shared__ float dxS[WPB][20];            // dv*x
    __shared__ float ssS[WPB][20];            // s = support@x
    __shared__ float blkAcc[2 * NN];

    const int tid  = threadIdx.x;
    const int lane = tid & 31;
    const int w    = tid >> 5;

    if (tid < 2 * NN) blkAcc[tid] = 0.f;
    __syncthreads();

    const float w1l = W1[lane];
    const float b1l = b1[lane];
    const float b2l = b2[lane];

    ull W2p[16];
    #pragma unroll
    for (int j = 0; j < 16; j++)
        W2p[j] = pk2(W2[(2 * j) * H + lane], W2[(2 * j + 1) * H + lane]);

    float sumP[NN], sqP[NN];
    #pragma unroll
    for (int n = 0; n < NN; n++) { sumP[n] = 0.f; sqP[n] = 0.f; }

    const unsigned aBase0 = (unsigned)__cvta_generic_to_shared(&adjS[w][0][0]);
    const unsigned aBase1 = (unsigned)__cvta_generic_to_shared(&adjS[w][1][0]);
    const unsigned xBase0 = (unsigned)__cvta_generic_to_shared(&xS[w][0][0]);
    const unsigned xBase1 = (unsigned)__cvta_generic_to_shared(&xS[w][1][0]);

    const long base = ((long)blockIdx.x * WPB + w) * SPW;

    // issue async loads of sample b into buffer bf
    auto issue = [&](long b, int bf) {
        const float* adjp = adj + b * (NN * NN);
        const unsigned ab = bf ? aBase1 : aBase0;
        const unsigned xb = bf ? xBase1 : xBase0;
        #pragma unroll
        for (int j = 0; j < 10; j++) {
            int idx = lane + 32 * j;
            if (idx < NN * NN) {
                int n = (idx * 3857) >> 16;         // idx/17 for idx<=288
                cp_async4(ab + (unsigned)(idx + 3 * n) * 4u, adjp + idx);
            }
        }
        if (lane < NN) cp_async4(xb + (unsigned)lane * 4u, x_str + b * NN + lane);
    };

    issue(base, 0);
    cp_commit();

    #pragma unroll 1
    for (int s = 0; s < SPW; s++) {
        const long b = base + s;
        cp_wait0();
        __syncwarp();

        const float* cur  = adjS[w][s & 1];
        const float* xcur = xS[w][s & 1];

        if (s + 1 < SPW) { issue(b + 1, (s + 1) & 1); cp_commit(); }

        // degrees of A_hat = adj + I ; dv = d^-1/2 ; dx = dv*x
        if (lane < NN) {
            float dg = 1.0f;
            #pragma unroll
            for (int m = 0; m < NN; m++) dg += cur[lane * 20 + m];
            float dv = dg > 0.f ? rsqrtf(dg) : 0.f;
            dS[w][lane]  = dv;
            dxS[w][lane] = dv * xcur[lane];
        }
        __syncwarp();

        // s[n] = dv[n] * ( sum_m A[n,m]*dx[m] + dx[n] )
        if (lane < NN) {
            float acc = 0.f;
            #pragma unroll
            for (int m = 0; m < NN; m++) acc += cur[lane * 20 + m] * dxS[w][m];
            ssS[w][lane] = dS[w][lane] * (acc + dxS[w][lane]);
        }
        __syncwarp();

        // h1d[m] = elu(s[m]*w1 + b1) * dv[m]   (this lane's hidden channel)
        float h1d[NN];
        #pragma unroll
        for (int m = 0; m < NN; m++)
            h1d[m] = elu_f(ssS[w][m] * w1l + b1l) * dS[w][m];
        ull h1p[8];
        #pragma unroll
        for (int j = 0; j < 8; j++) h1p[j] = pk2(h1d[2 * j], h1d[2 * j + 1]);
        const float h1d16 = h1d[16];

        // agg[n] = dv[n] * ( sum_m A[n,m]*h1d[m] + h1d[n] )
        #pragma unroll
        for (int n = 0; n < NN; n++) {
            const ulonglong2* av = reinterpret_cast<const ulonglong2*>(&cur[n * 20]);
            ull a0 = 0ull, a1 = 0ull;
            #pragma unroll
            for (int q = 0; q < 4; q++) {
                ulonglong2 v = av[q];
                ffma2(a0, v.x, h1p[2 * q]);
                ffma2(a1, v.y, h1p[2 * q + 1]);
            }
            float l0, hh0, l1, hh1;
            upk2(a0, l0, hh0); upk2(a1, l1, hh1);
            float acc = (l0 + hh0) + (l1 + hh1) + cur[n * 20 + 16] * h1d16 + h1d[n];
            bufS[w][n * 36 + lane] = acc * dS[w][n];
        }
        __syncwarp();

        // t = agg @ W2 + b2 ; h2 = elu(t) ; fp16 store + stats
        __half* outp = gH2h + b * (NN * H);
        #pragma unroll
        for (int n = 0; n < NN; n++) {
            const ulonglong2* bv = reinterpret_cast<const ulonglong2*>(&bufS[w][n * 36]);
            ull a0 = 0ull, a1 = 0ull;
            #pragma unroll
            for (int q = 0; q < 8; q++) {
                ulonglong2 v = bv[q];
                ffma2(a0, v.x, W2p[2 * q]);
                ffma2(a1, v.y, W2p[2 * q + 1]);
            }
            float l0, hh0, l1, hh1;
            upk2(a0, l0, hh0); upk2(a1, l1, hh1);
            float h2 = elu_f((l0 + hh0) + (l1 + hh1) + b2l);
            outp[n * H + lane] = __float2half(h2);
            sumP[n] += h2;
            sqP[n]  += h2 * h2;
        }
        __syncwarp();
    }

    // warp butterfly reduce stats
    #pragma unroll
    for (int n = 0; n < NN; n++) {
        #pragma unroll
        for (int off = 16; off; off >>= 1) {
            sumP[n] += __shfl_xor_sync(0xffffffffu, sumP[n], off);
            sqP[n]  += __shfl_xor_sync(0xffffffffu, sqP[n],  off);
        }
    }
    if (lane == 0) {
        #pragma unroll
        for (int n = 0; n < NN; n++) {
            atomicAdd(&blkAcc[n], sumP[n]);
            atomicAdd(&blkAcc[NN + n], sqP[n]);
        }
    }
    __syncthreads();
    if (tid < NN)           atomicAdd(&gSum[tid],      blkAcc[tid]);
    else if (tid < 2 * NN)  atomicAdd(&gSq[tid - NN],  blkAcc[tid]);
}

// ---------------------------------------------------------------------------
__global__ void finalize_kernel(const float* __restrict__ gamma,
                                const float* __restrict__ beta)
{
    int n = threadIdx.x;
    float Cl = 0.f;
    if (n < NN) {
        const float inv_cnt = 1.f / ((float)B_TOT * (float)H);
        float mean = gSum[n] * inv_cnt;
        float var  = gSq[n] * inv_cnt - mean * mean;
        float rs   = rsqrtf(var + EPS);
        float A    = gamma[n] * rs;
        float C    = beta[n] - mean * A;
        gA[n] = A * (1.f / 17.f);
        Cl    = C * (1.f / 17.f);
    }
    #pragma unroll
    for (int off = 16; off; off >>= 1) Cl += __shfl_xor_sync(0xffffffffu, Cl, off);
    if (n == 0) gCbar = Cl;
}

// ---------------------------------------------------------------------------
// Pass 2: BN-fold + node mean + MLP head. 128-thread blocks (4 warps).
// Weights read straight from global (L1-resident, broadcast); only comb in smem.
#define P2_WARPS 4
#define CSTRIDE  53

__global__ __launch_bounds__(128) void pass2_kernel(
    const float* __restrict__ x_raw,   // [B,17]
    const float* __restrict__ x_cov,   // [B,3]
    const float* __restrict__ age,     // [B,1]
    const float* __restrict__ Wr1,     // [53,64]
    const float* __restrict__ br1,     // [64]
    const float* __restrict__ Wr2,     // [64,32]
    const float* __restrict__ br2,     // [32]
    const float* __restrict__ Wr3,     // [32,1]
    const float* __restrict__ br3,     // [1]
    float* __restrict__ out)           // [B,1]
{
    __shared__ float combS[P2_WARPS * 32 * CSTRIDE];   // 27136 B

    const int tid  = threadIdx.x;
    const int lane = tid & 31;
    const int w    = tid >> 5;
    float* comb = combS + w * (32 * CSTRIDE);
    const long base = ((long)blockIdx.x * P2_WARPS + w) * 32;

    float As_r[NN];
    #pragma unroll
    for (int n = 0; n < NN; n++) As_r[n] = gA[n];
    const float cbar = gCbar;

    // ---- Phase A: build comb rows (fp32) for this warp's 32 samples ----
    #pragma unroll 1
    for (int s2 = 0; s2 < 32; s2++) {
        const long b = base + s2;
        const __half* hp = gH2h + b * (NN * H);
        float ge = cbar;
        #pragma unroll
        for (int n = 0; n < NN; n++)
            ge += As_r[n] * __half2float(hp[n * H + lane]);
        comb[s2 * CSTRIDE + lane] = ge;
        if (lane < NN)
            comb[s2 * CSTRIDE + 32 + lane] = x_raw[b * NN + lane];
        else if (lane < 20)
            comb[s2 * CSTRIDE + 32 + lane] = x_cov[b * 3 + (lane - NN)];
        else if (lane == 20)
            comb[s2 * CSTRIDE + 52] = age[b];
    }
    __syncwarp();

    // ---- Phase B: lane = sample; chunked layer1 fused into layer2 ----
    const long b = base + lane;
    const float* cl = comb + lane * CSTRIDE;   // odd stride: conflict-free

    ull z2a[16];
    const ull* b2u = reinterpret_cast<const ull*>(br2);
    #pragma unroll
    for (int j = 0; j < 16; j++) z2a[j] = b2u[j];

    #pragma unroll
    for (int c = 0; c < 4; c++) {
        // layer1 chunk: outputs [16c, 16c+16)
        ull za[8];
        const ull* b1u = reinterpret_cast<const ull*>(br1 + 16 * c);
        #pragma unroll
        for (int j = 0; j < 8; j++) za[j] = b1u[j];

        #pragma unroll 1
        for (int p = 0; p < 26; p++) {                 // inputs 0..51 in pairs
            float f0 = cl[2 * p];
            float f1 = cl[2 * p + 1];
            ull ca = pk2(f0, f0);
            ull cb = pk2(f1, f1);
            const ulonglong2* wa = reinterpret_cast<const ulonglong2*>(Wr1 + (2 * p) * 64 + 16 * c);
            const ulonglong2* wb = reinterpret_cast<const ulonglong2*>(Wr1 + (2 * p + 1) * 64 + 16 * c);
            #pragma unroll
            for (int q = 0; q < 4; q++) {
                ulonglong2 va = wa[q];
                ffma2(za[2 * q],     ca, va.x);
                ffma2(za[2 * q + 1], ca, va.y);
            }
            #pragma unroll
            for (int q = 0; q < 4; q++) {
                ulonglong2 vb = wb[q];
                ffma2(za[2 * q],     cb, vb.x);
                ffma2(za[2 * q + 1], cb, vb.y);
            }
        }
        {   // input 52
            float ci = cl[52];
            ull c2 = pk2(ci, ci);
            const ulonglong2* wv = reinterpret_cast<const ulonglong2*>(Wr1 + 52 * 64 + 16 * c);
            #pragma unroll
            for (int q = 0; q < 4; q++) {
                ulonglong2 v = wv[q];
                ffma2(za[2 * q],     c2, v.x);
                ffma2(za[2 * q + 1], c2, v.y);
            }
        }

        // ReLU chunk, fold into layer2 accumulators
        #pragma unroll
        for (int j = 0; j < 8; j++) {
            float r0, r1; upk2(za[j], r0, r1);
            r0 = fmaxf(r0, 0.f); r1 = fmaxf(r1, 0.f);
            int k0 = 16 * c + 2 * j;
            ull ca = pk2(r0, r0);
            ull cb = pk2(r1, r1);
            const ulonglong2* wa = reinterpret_cast<const ulonglong2*>(Wr2 + k0 * 32);
            const ulonglong2* wb = reinterpret_cast<const ulonglong2*>(Wr2 + (k0 + 1) * 32);
            #pragma unroll
            for (int q = 0; q < 8; q++) {
                ulonglong2 va = wa[q];
                ffma2(z2a[2 * q],     ca, va.x);
                ffma2(z2a[2 * q + 1], ca, va.y);
            }
            #pragma unroll
            for (int q = 0; q < 8; q++) {
                ulonglong2 vb = wb[q];
                ffma2(z2a[2 * q],     cb, vb.x);
                ffma2(z2a[2 * q + 1], cb, vb.y);
            }
        }
    }

    // layer 3: 32 -> 1
    float acc = br3[0];
    #pragma unroll
    for (int j = 0; j < 16; j++) {
        float lo, hi; upk2(z2a[j], lo, hi);
        acc += fmaxf(lo, 0.f) * Wr3[2 * j];
        acc += fmaxf(hi, 0.f) * Wr3[2 * j + 1];
    }
    out[b] = 1.f / (1.f + __expf(-acc));
}

// ---------------------------------------------------------------------------
extern "C" void kernel_launch(void* const* d_in, const int* in_sizes, int n_in,
                              void* d_out, int out_size)
{
    const float* x_str = (const float*)d_in[0];
    const float* x_raw = (const float*)d_in[1];
    const float* adj   = (const float*)d_in[2];
    const float* x_cov = (const float*)d_in[3];
    const float* age   = (const float*)d_in[4];
    const float* W1    = (const float*)d_in[5];
    const float* b1    = (const float*)d_in[6];
    const float* W2    = (const float*)d_in[7];
    const float* b2    = (const float*)d_in[8];
    const float* gamma = (const float*)d_in[9];
    const float* beta  = (const float*)d_in[10];
    const float* Wr1   = (const float*)d_in[11];
    const float* br1   = (const float*)d_in[12];
    const float* Wr2   = (const float*)d_in[13];
    const float* br2   = (const float*)d_in[14];
    const float* Wr3   = (const float*)d_in[15];
    const float* br3   = (const float*)d_in[16];

    const int blocks1 = B_TOT / (WPB * SPW);          // 2048
    const int blocks2 = B_TOT / (P2_WARPS * 32);      // 1024

    zero_stats_kernel<<<1, 32>>>();
    pass1_kernel<<<blocks1, 256>>>(x_str, adj, W1, b1, W2, b2);
    finalize_kernel<<<1, 32>>>(gamma, beta);
    pass2_kernel<<<blocks2, 128>>>(x_raw, x_cov, age,
                                   Wr1, br1, Wr2, br2, Wr3, br3,
                                   (float*)d_out);
}

// round 7
// speedup vs baseline: 1.3810x; 1.1689x over previous
#include <cuda_runtime.h>
#include <cuda_fp16.h>
#include <math.h>

#define B_TOT   131072
#define NN      17
#define H       32
#define EPS     1e-5f
#define D_IN    53
#define WPB     8           // warps per block (pass1)
#define SPW     8           // samples per warp (pass1)

// ---------------- scratch (device globals; no allocation allowed) ------------
__device__ __half gH2h[(size_t)B_TOT * NN * H];   // 142 MB fp16 staging of h2
__device__ float gSum[NN];
__device__ float gSq[NN];
__device__ float gA[NN];     // gamma*rsqrt(var+eps)/17
__device__ float gCbar;      // sum_n (beta - mean*A)/17

// ---------------- packed f32x2 helpers ---------------------------------------
typedef unsigned long long ull;

__device__ __forceinline__ ull pk2(float lo, float hi) {
    ull r; asm("mov.b64 %0,{%1,%2};" : "=l"(r) : "f"(lo), "f"(hi)); return r;
}
__device__ __forceinline__ void upk2(ull v, float& lo, float& hi) {
    asm("mov.b64 {%0,%1},%2;" : "=f"(lo), "=f"(hi) : "l"(v));
}
__device__ __forceinline__ void ffma2(ull& d, ull a, ull b) {
    asm("fma.rn.f32x2 %0,%1,%2,%0;" : "+l"(d) : "l"(a), "l"(b));
}

__device__ __forceinline__ float elu_f(float x) {
    return fmaxf(x, 0.f) + (__expf(fminf(x, 0.f)) - 1.f);
}

// ---------------- cp.async helpers -------------------------------------------
__device__ __forceinline__ void cp_async4(unsigned dst, const float* src) {
    asm volatile("cp.async.ca.shared.global [%0], [%1], 4;" :: "r"(dst), "l"(src));
}
__device__ __forceinline__ void cp_commit() {
    asm volatile("cp.async.commit_group;" ::: "memory");
}
__device__ __forceinline__ void cp_wait0() {
    asm volatile("cp.async.wait_group 0;" ::: "memory");
}

// ---------------------------------------------------------------------------
__global__ void zero_stats_kernel() {
    int t = threadIdx.x;
    if (t < NN) { gSum[t] = 0.f; gSq[t] = 0.f; }
}

// ---------------------------------------------------------------------------
// Pass 1: per-sample 2-layer GCN, h2 -> gH2h (fp16). NO stats here (separate
// streaming kernel) so register count permits 3 blocks/SM.
__global__ __launch_bounds__(256, 3) void pass1_kernel(
    const float* __restrict__ x_str,   // [B,17,1]
    const float* __restrict__ adj,     // [B,17,17]
    const float* __restrict__ W1,      // [1,32]
    const float* __restrict__ b1,      // [32]
    const float* __restrict__ W2,      // [32,32]
    const float* __restrict__ b2)      // [32]
{
    __shared__ float adjS[WPB][2][NN * 20];   // raw adj, padded rows, 2 buffers
    __shared__ float xS[WPB][2][20];
    __shared__ float bufS[WPB][NN * 36];      // agg staging, row stride 36
    __shared__ float dS[WPB][20];             // dv
    __shared__ float dxS[WPB][20];            // dv*x
    __shared__ float ssS[WPB][20];            // s = support@x

    const int tid  = threadIdx.x;
    const int lane = tid & 31;
    const int w    = tid >> 5;

    const float w1l = W1[lane];
    const float b1l = b1[lane];
    const float b2l = b2[lane];

    ull W2p[16];
    #pragma unroll
    for (int j = 0; j < 16; j++)
        W2p[j] = pk2(W2[(2 * j) * H + lane], W2[(2 * j + 1) * H + lane]);

    const unsigned aBase0 = (unsigned)__cvta_generic_to_shared(&adjS[w][0][0]);
    const unsigned aBase1 = (unsigned)__cvta_generic_to_shared(&adjS[w][1][0]);
    const unsigned xBase0 = (unsigned)__cvta_generic_to_shared(&xS[w][0][0]);
    const unsigned xBase1 = (unsigned)__cvta_generic_to_shared(&xS[w][1][0]);

    const long base = ((long)blockIdx.x * WPB + w) * SPW;

    // issue async loads of sample b into buffer bf
    auto issue = [&](long b, int bf) {
        const float* adjp = adj + b * (NN * NN);
        const unsigned ab = bf ? aBase1 : aBase0;
        const unsigned xb = bf ? xBase1 : xBase0;
        #pragma unroll
        for (int j = 0; j < 10; j++) {
            int idx = lane + 32 * j;
            if (idx < NN * NN) {
                int n = (idx * 3857) >> 16;         // idx/17 for idx<=288
                cp_async4(ab + (unsigned)(idx + 3 * n) * 4u, adjp + idx);
            }
        }
        if (lane < NN) cp_async4(xb + (unsigned)lane * 4u, x_str + b * NN + lane);
    };

    issue(base, 0);
    cp_commit();

    #pragma unroll 1
    for (int s = 0; s < SPW; s++) {
        const long b = base + s;
        cp_wait0();
        __syncwarp();

        const float* cur  = adjS[w][s & 1];
        const float* xcur = xS[w][s & 1];

        if (s + 1 < SPW) { issue(b + 1, (s + 1) & 1); cp_commit(); }

        // degrees of A_hat = adj + I ; dv = d^-1/2 ; dx = dv*x
        if (lane < NN) {
            float dg = 1.0f;
            #pragma unroll
            for (int m = 0; m < NN; m++) dg += cur[lane * 20 + m];
            float dv = dg > 0.f ? rsqrtf(dg) : 0.f;
            dS[w][lane]  = dv;
            dxS[w][lane] = dv * xcur[lane];
        }
        __syncwarp();

        // s[n] = dv[n] * ( sum_m A[n,m]*dx[m] + dx[n] )
        if (lane < NN) {
            float acc = 0.f;
            #pragma unroll
            for (int m = 0; m < NN; m++) acc += cur[lane * 20 + m] * dxS[w][m];
            ssS[w][lane] = dS[w][lane] * (acc + dxS[w][lane]);
        }
        __syncwarp();

        // h1d[m] = elu(s[m]*w1 + b1) * dv[m]   (this lane's hidden channel)
        float h1d[NN];
        #pragma unroll
        for (int m = 0; m < NN; m++)
            h1d[m] = elu_f(ssS[w][m] * w1l + b1l) * dS[w][m];
        ull h1p[8];
        #pragma unroll
        for (int j = 0; j < 8; j++) h1p[j] = pk2(h1d[2 * j], h1d[2 * j + 1]);
        const float h1d16 = h1d[16];

        // agg[n] = dv[n] * ( sum_m A[n,m]*h1d[m] + h1d[n] )
        #pragma unroll
        for (int n = 0; n < NN; n++) {
            const ulonglong2* av = reinterpret_cast<const ulonglong2*>(&cur[n * 20]);
            ull a0 = 0ull, a1 = 0ull;
            #pragma unroll
            for (int q = 0; q < 4; q++) {
                ulonglong2 v = av[q];
                ffma2(a0, v.x, h1p[2 * q]);
                ffma2(a1, v.y, h1p[2 * q + 1]);
            }
            float l0, hh0, l1, hh1;
            upk2(a0, l0, hh0); upk2(a1, l1, hh1);
            float acc = (l0 + hh0) + (l1 + hh1) + cur[n * 20 + 16] * h1d16 + h1d[n];
            bufS[w][n * 36 + lane] = acc * dS[w][n];
        }
        __syncwarp();

        // t = agg @ W2 + b2 ; h2 = elu(t) ; fp16 store
        __half* outp = gH2h + b * (NN * H);
        #pragma unroll
        for (int n = 0; n < NN; n++) {
            const ulonglong2* bv = reinterpret_cast<const ulonglong2*>(&bufS[w][n * 36]);
            ull a0 = 0ull, a1 = 0ull;
            #pragma unroll
            for (int q = 0; q < 8; q++) {
                ulonglong2 v = bv[q];
                ffma2(a0, v.x, W2p[2 * q]);
                ffma2(a1, v.y, W2p[2 * q + 1]);
            }
            float l0, hh0, l1, hh1;
            upk2(a0, l0, hh0); upk2(a1, l1, hh1);
            float h2 = elu_f((l0 + hh0) + (l1 + hh1) + b2l);
            outp[n * H + lane] = __float2half(h2);
        }
        __syncwarp();
    }
}

// ---------------------------------------------------------------------------
// Streaming BN-stats over gH2h. 272 threads: thread t owns half2 slot t of each
// sample (n = t/16). Coalesced 128B warp reads; fp32 local accum then atomics.
__global__ __launch_bounds__(272) void stats_kernel() {
    __shared__ float sAcc[2 * NN];
    const int t = threadIdx.x;               // 0..271
    if (t < 2 * NN) sAcc[t] = 0.f;
    __syncthreads();

    const int n = t >> 4;
    const __half2* p = reinterpret_cast<const __half2*>(gH2h);
    float sum = 0.f, sq = 0.f;
    for (long b = blockIdx.x; b < B_TOT; b += gridDim.x) {
        float2 v = __half22float2(p[b * 272 + t]);
        sum += v.x + v.y;
        sq  += v.x * v.x + v.y * v.y;
    }
    atomicAdd(&sAcc[n], sum);
    atomicAdd(&sAcc[NN + n], sq);
    __syncthreads();
    if (t < NN)           atomicAdd(&gSum[t],      sAcc[t]);
    else if (t < 2 * NN)  atomicAdd(&gSq[t - NN],  sAcc[t]);
}

// ---------------------------------------------------------------------------
__global__ void finalize_kernel(const float* __restrict__ gamma,
                                const float* __restrict__ beta)
{
    int n = threadIdx.x;
    float Cl = 0.f;
    if (n < NN) {
        const float inv_cnt = 1.f / ((float)B_TOT * (float)H);
        float mean = gSum[n] * inv_cnt;
        float var  = gSq[n] * inv_cnt - mean * mean;
        float rs   = rsqrtf(var + EPS);
        float A    = gamma[n] * rs;
        float C    = beta[n] - mean * A;
        gA[n] = A * (1.f / 17.f);
        Cl    = C * (1.f / 17.f);
    }
    #pragma unroll
    for (int off = 16; off; off >>= 1) Cl += __shfl_xor_sync(0xffffffffu, Cl, off);
    if (n == 0) gCbar = Cl;
}

// ---------------------------------------------------------------------------
// Pass 2: BN-fold + node mean + MLP head. 128-thread blocks (4 warps).
// Shared: weights + ge staging only (stride 33). Raw features read to regs in
// Phase B. 39.2 KB static smem -> 5 blocks/SM.
#define P2_WARPS 4
#define GESTRIDE 33

__global__ __launch_bounds__(128) void pass2_kernel(
    const float* __restrict__ x_raw,   // [B,17]
    const float* __restrict__ x_cov,   // [B,3]
    const float* __restrict__ age,     // [B,1]
    const float* __restrict__ Wr1,     // [53,64]
    const float* __restrict__ br1,     // [64]
    const float* __restrict__ Wr2,     // [64,32]
    const float* __restrict__ br2,     // [32]
    const float* __restrict__ Wr3,     // [32,1]
    const float* __restrict__ br3,     // [1]
    float* __restrict__ out)           // [B,1]
{
    __shared__ __align__(16) float Wr1s[D_IN * 64];             // 13568 B
    __shared__ __align__(16) float Wr2s[64 * H];                //  8192 B
    __shared__ __align__(16) float geS[P2_WARPS][32 * GESTRIDE];// 16896 B
    __shared__ __align__(16) float br1s[64];
    __shared__ __align__(16) float br2s[H];
    __shared__ __align__(16) float wr3s[H];
    __shared__ float As_[NN + 1];
    __shared__ float misc[2];

    const int tid = threadIdx.x;
    for (int i = tid; i < D_IN * 64; i += 128) Wr1s[i] = Wr1[i];
    for (int i = tid; i < 64 * H;   i += 128) Wr2s[i] = Wr2[i];
    if (tid < 64) br1s[tid] = br1[tid];
    if (tid < 32) { br2s[tid] = br2[tid]; wr3s[tid] = Wr3[tid]; }
    if (tid < NN) As_[tid] = gA[tid];
    if (tid == 0) { misc[0] = gCbar; misc[1] = br3[0]; }
    __syncthreads();

    const int lane = tid & 31;
    const int w    = tid >> 5;
    float* ge = geS[w];
    const long base = ((long)blockIdx.x * P2_WARPS + w) * 32;

    float As_r[NN];
    #pragma unroll
    for (int n = 0; n < NN; n++) As_r[n] = As_[n];
    const float cbar = misc[0];

    // ---- Phase A: graph_emb (BN-folded) for this warp's 32 samples ----
    #pragma unroll 1
    for (int s2 = 0; s2 < 32; s2++) {
        const __half* hp = gH2h + (base + s2) * (NN * H);
        float g = cbar;
        #pragma unroll
        for (int n = 0; n < NN; n++)
            g += As_r[n] * __half2float(hp[n * H + lane]);
        ge[s2 * GESTRIDE + lane] = g;
    }
    __syncwarp();

    // ---- Phase B: lane = sample ----
    const long b = base + lane;
    const float* cl = ge + lane * GESTRIDE;    // stride 33: conflict-free

    // raw features to registers
    float xr[21];
    {
        const float* xrp = x_raw + b * NN;
        #pragma unroll
        for (int i = 0; i < NN; i++) xr[i] = xrp[i];
        const float* xcp = x_cov + b * 3;
        xr[17] = xcp[0]; xr[18] = xcp[1]; xr[19] = xcp[2];
        xr[20] = age[b];
    }

    ull z2a[16];
    const ull* b2u = reinterpret_cast<const ull*>(br2s);
    #pragma unroll
    for (int j = 0; j < 16; j++) z2a[j] = b2u[j];

    #pragma unroll
    for (int c = 0; c < 4; c++) {
        // layer1 chunk: outputs [16c, 16c+16)
        ull za[8];
        const ull* b1u = reinterpret_cast<const ull*>(br1s + 16 * c);
        #pragma unroll
        for (int j = 0; j < 8; j++) za[j] = b1u[j];

        // inputs 0..31 (graph_emb) from shared, in pairs
        #pragma unroll 1
        for (int p = 0; p < 16; p++) {
            float f0 = cl[2 * p];
            float f1 = cl[2 * p + 1];
            ull ca = pk2(f0, f0);
            ull cb = pk2(f1, f1);
            const ulonglong2* wa = reinterpret_cast<const ulonglong2*>(&Wr1s[(2 * p) * 64 + 16 * c]);
            const ulonglong2* wb = reinterpret_cast<const ulonglong2*>(&Wr1s[(2 * p + 1) * 64 + 16 * c]);
            #pragma unroll
            for (int q = 0; q < 4; q++) {
                ulonglong2 va = wa[q];
                ffma2(za[2 * q],     ca, va.x);
                ffma2(za[2 * q + 1], ca, va.y);
            }
            #pragma unroll
            for (int q = 0; q < 4; q++) {
                ulonglong2 vb = wb[q];
                ffma2(za[2 * q],     cb, vb.x);
                ffma2(za[2 * q + 1], cb, vb.y);
            }
        }
        // inputs 32..51 (raw features) from registers, in pairs
        #pragma unroll 1
        for (int p = 0; p < 10; p++) {
            float f0 = xr[2 * p];
            float f1 = xr[2 * p + 1];
            ull ca = pk2(f0, f0);
            ull cb = pk2(f1, f1);
            const ulonglong2* wa = reinterpret_cast<const ulonglong2*>(&Wr1s[(32 + 2 * p) * 64 + 16 * c]);
            const ulonglong2* wb = reinterpret_cast<const ulonglong2*>(&Wr1s[(33 + 2 * p) * 64 + 16 * c]);
            #pragma unroll
            for (int q = 0; q < 4; q++) {
                ulonglong2 va = wa[q];
                ffma2(za[2 * q],     ca, va.x);
                ffma2(za[2 * q + 1], ca, va.y);
            }
            #pragma unroll
            for (int q = 0; q < 4; q++) {
                ulonglong2 vb = wb[q];
                ffma2(za[2 * q],     cb, vb.x);
                ffma2(za[2 * q + 1], cb, vb.y);
            }
        }
        {   // input 52 (= xr[20])
            float ci = xr[20];
            ull c2 = pk2(ci, ci);
            const ulonglong2* wv = reinterpret_cast<const ulonglong2*>(&Wr1s[52 * 64 + 16 * c]);
            #pragma unroll
            for (int q = 0; q < 4; q++) {
                ulonglong2 v = wv[q];
                ffma2(za[2 * q],     c2, v.x);
                ffma2(za[2 * q + 1], c2, v.y);
            }
        }

        // ReLU chunk, fold into layer2 accumulators
        #pragma unroll
        for (int j = 0; j < 8; j++) {
            float r0, r1; upk2(za[j], r0, r1);
            r0 = fmaxf(r0, 0.f); r1 = fmaxf(r1, 0.f);
            int k0 = 16 * c + 2 * j;
            ull ca = pk2(r0, r0);
            ull cb = pk2(r1, r1);
            const ulonglong2* wa = reinterpret_cast<const ulonglong2*>(&Wr2s[k0 * 32]);
            const ulonglong2* wb = reinterpret_cast<const ulonglong2*>(&Wr2s[(k0 + 1) * 32]);
            #pragma unroll
            for (int q = 0; q < 8; q++) {
                ulonglong2 va = wa[q];
                ffma2(z2a[2 * q],     ca, va.x);
                ffma2(z2a[2 * q + 1], ca, va.y);
            }
            #pragma unroll
            for (int q = 0; q < 8; q++) {
                ulonglong2 vb = wb[q];
                ffma2(z2a[2 * q],     cb, vb.x);
                ffma2(z2a[2 * q + 1], cb, vb.y);
            }
        }
    }

    // layer 3: 32 -> 1
    float acc = misc[1];
    #pragma unroll
    for (int j = 0; j < 16; j++) {
        float lo, hi; upk2(z2a[j], lo, hi);
        acc += fmaxf(lo, 0.f) * wr3s[2 * j];
        acc += fmaxf(hi, 0.f) * wr3s[2 * j + 1];
    }
    out[b] = 1.f / (1.f + __expf(-acc));
}

// ---------------------------------------------------------------------------
extern "C" void kernel_launch(void* const* d_in, const int* in_sizes, int n_in,
                              void* d_out, int out_size)
{
    const float* x_str = (const float*)d_in[0];
    const float* x_raw = (const float*)d_in[1];
    const float* adj   = (const float*)d_in[2];
    const float* x_cov = (const float*)d_in[3];
    const float* age   = (const float*)d_in[4];
    const float* W1    = (const float*)d_in[5];
    const float* b1    = (const float*)d_in[6];
    const float* W2    = (const float*)d_in[7];
    const float* b2    = (const float*)d_in[8];
    const float* gamma = (const float*)d_in[9];
    const float* beta  = (const float*)d_in[10];
    const float* Wr1   = (const float*)d_in[11];
    const float* br1   = (const float*)d_in[12];
    const float* Wr2   = (const float*)d_in[13];
    const float* br2   = (const float*)d_in[14];
    const float* Wr3   = (const float*)d_in[15];
    const float* br3   = (const float*)d_in[16];

    const int blocks1 = B_TOT / (WPB * SPW);          // 2048
    const int blocks2 = B_TOT / (P2_WARPS * 32);      // 1024

    zero_stats_kernel<<<1, 32>>>();
    pass1_kernel<<<blocks1, 256>>>(x_str, adj, W1, b1, W2, b2);
    stats_kernel<<<2048, 272>>>();
    finalize_kernel<<<1, 32>>>(gamma, beta);
    pass2_kernel<<<blocks2, 128>>>(x_raw, x_cov, age,
                                   Wr1, br1, Wr2, br2, Wr3, br3,
                                   (float*)d_out);
}

// round 9
// speedup vs baseline: 1.5218x; 1.1020x over previous
#include <cuda_runtime.h>
#include <cuda_fp16.h>
#include <math.h>

#define B_TOT   131072
#define NN      17
#define H       32
#define EPS     1e-5f
#define D_IN    53
#define WPB     8           // warps per block (pass1)
#define SPW     8           // samples per warp (pass1)

// ---------------- scratch (device globals; no allocation allowed) ------------
__device__ __half gH2h[(size_t)B_TOT * NN * H];   // 142 MB fp16 staging of h2
__device__ float gSum[NN];
__device__ float gSq[NN];
__device__ float gA[NN];     // gamma*rsqrt(var+eps)/17
__device__ float gCbar;      // sum_n (beta - mean*A)/17

// ---------------- packed f32x2 helpers ---------------------------------------
typedef unsigned long long ull;

__device__ __forceinline__ ull pk2(float lo, float hi) {
    ull r; asm("mov.b64 %0,{%1,%2};" : "=l"(r) : "f"(lo), "f"(hi)); return r;
}
__device__ __forceinline__ void upk2(ull v, float& lo, float& hi) {
    asm("mov.b64 {%0,%1},%2;" : "=f"(lo), "=f"(hi) : "l"(v));
}
__device__ __forceinline__ void ffma2(ull& d, ull a, ull b) {
    asm("fma.rn.f32x2 %0,%1,%2,%0;" : "+l"(d) : "l"(a), "l"(b));
}
// extract element n (0..15) from pack array; n is compile-time constant at use
__device__ __forceinline__ float getp(const ull* p, int n) {
    float lo, hi; upk2(p[n >> 1], lo, hi);
    return (n & 1) ? hi : lo;
}

__device__ __forceinline__ float elu_f(float x) {
    return fmaxf(x, 0.f) + (__expf(fminf(x, 0.f)) - 1.f);
}

// ---------------- cp.async helpers -------------------------------------------
__device__ __forceinline__ void cp_async4(unsigned dst, const float* src) {
    asm volatile("cp.async.ca.shared.global [%0], [%1], 4;" :: "r"(dst), "l"(src));
}
__device__ __forceinline__ void cp_commit() {
    asm volatile("cp.async.commit_group;" ::: "memory");
}
__device__ __forceinline__ void cp_wait0() {
    asm volatile("cp.async.wait_group 0;" ::: "memory");
}

// ---------------------------------------------------------------------------
__global__ void zero_stats_kernel() {
    int t = threadIdx.x;
    if (t < NN) { gSum[t] = 0.f; gSq[t] = 0.f; }
}

// ---------------------------------------------------------------------------
// Pass 1: per-sample 2-layer GCN, h2 -> gH2h (fp16). Two samples processed
// concurrently per warp (A/B) to double independent work between syncs.
#define P1_ADJ   0
#define P1_X     (P1_ADJ + WPB*4*NN*20)
#define P1_BUF   (P1_X   + WPB*4*20)
#define P1_D     (P1_BUF + WPB*2*NN*36)
#define P1_DX    (P1_D   + WPB*2*20)
#define P1_SS    (P1_DX  + WPB*2*20)
#define P1_FLOATS (P1_SS + WPB*2*20)

__global__ __launch_bounds__(256, 2) void pass1_kernel(
    const float* __restrict__ x_str,   // [B,17,1]
    const float* __restrict__ adj,     // [B,17,17]
    const float* __restrict__ W1,      // [1,32]
    const float* __restrict__ b1,      // [32]
    const float* __restrict__ W2,      // [32,32]
    const float* __restrict__ b2)      // [32]
{
    extern __shared__ float sm1[];

    const int tid  = threadIdx.x;
    const int lane = tid & 31;
    const int w    = tid >> 5;

    float* adjW = sm1 + P1_ADJ + w * (4 * NN * 20);
    float* xW   = sm1 + P1_X   + w * (4 * 20);
    float* bufA = sm1 + P1_BUF + w * (2 * NN * 36);
    float* bufB = bufA + NN * 36;
    float* dA   = sm1 + P1_D   + w * 40;
    float* dB   = dA + 20;
    float* dxA  = sm1 + P1_DX  + w * 40;
    float* dxB  = dxA + 20;
    float* ssA  = sm1 + P1_SS  + w * 40;
    float* ssB  = ssA + 20;

    const float w1l = W1[lane];
    const float b1l = b1[lane];
    const float b2l = b2[lane];

    ull W2p[16];
    #pragma unroll
    for (int j = 0; j < 16; j++)
        W2p[j] = pk2(W2[(2 * j) * H + lane], W2[(2 * j + 1) * H + lane]);

    const long base = ((long)blockIdx.x * WPB + w) * SPW;

    // issue async loads of sample b into rotating buffer bf (0..3)
    auto issue = [&](long b, int bf) {
        const float* adjp = adj + b * (NN * NN);
        const unsigned ab = (unsigned)__cvta_generic_to_shared(adjW + bf * (NN * 20));
        const unsigned xb = (unsigned)__cvta_generic_to_shared(xW + bf * 20);
        #pragma unroll
        for (int j = 0; j < 10; j++) {
            int idx = lane + 32 * j;
            if (idx < NN * NN) {
                int n = (idx * 3857) >> 16;         // idx/17 for idx<=288
                cp_async4(ab + (unsigned)(idx + 3 * n) * 4u, adjp + idx);
            }
        }
        if (lane < NN) cp_async4(xb + (unsigned)lane * 4u, x_str + b * NN + lane);
    };

    issue(base + 0, 0);
    issue(base + 1, 1);
    cp_commit();

    #pragma unroll 1
    for (int p = 0; p < SPW / 2; p++) {
        const long bA = base + 2 * p;
        const long bB = bA + 1;
        cp_wait0();
        __syncwarp();

        const float* curA = adjW + ((2 * p) & 3) * (NN * 20);
        const float* curB = adjW + ((2 * p + 1) & 3) * (NN * 20);
        const float* xA   = xW + ((2 * p) & 3) * 20;
        const float* xB   = xW + ((2 * p + 1) & 3) * 20;

        if (p + 1 < SPW / 2) {
            issue(bA + 2, (2 * p + 2) & 3);
            issue(bB + 2, (2 * p + 3) & 3);
            cp_commit();
        }

        // degrees of A_hat = adj + I ; dv = d^-1/2 ; dx = dv*x  (A and B)
        if (lane < NN) {
            float dgA = 1.0f, dgB = 1.0f;
            #pragma unroll
            for (int m = 0; m < NN; m++) {
                dgA += curA[lane * 20 + m];
                dgB += curB[lane * 20 + m];
            }
            float dvA = dgA > 0.f ? rsqrtf(dgA) : 0.f;
            float dvB = dgB > 0.f ? rsqrtf(dgB) : 0.f;
            dA[lane]  = dvA;  dxA[lane] = dvA * xA[lane];
            dB[lane]  = dvB;  dxB[lane] = dvB * xB[lane];
        }
        __syncwarp();

        // s[n] = dv[n] * ( sum_m A[n,m]*dx[m] + dx[n] )
        if (lane < NN) {
            float accA = 0.f, accB = 0.f;
            #pragma unroll
            for (int m = 0; m < NN; m++) {
                accA += curA[lane * 20 + m] * dxA[m];
                accB += curB[lane * 20 + m] * dxB[m];
            }
            ssA[lane] = dA[lane] * (accA + dxA[lane]);
            ssB[lane] = dB[lane] * (accB + dxB[lane]);
        }
        __syncwarp();

        // h1d[m] = elu(s[m]*w1 + b1) * dv[m], packed (this lane's channel)
        ull h1pA[8], h1pB[8];
        float h16A, h16B;
        {
            #pragma unroll
            for (int j = 0; j < 8; j++) {
                float a0 = elu_f(ssA[2 * j] * w1l + b1l) * dA[2 * j];
                float a1 = elu_f(ssA[2 * j + 1] * w1l + b1l) * dA[2 * j + 1];
                float c0 = elu_f(ssB[2 * j] * w1l + b1l) * dB[2 * j];
                float c1 = elu_f(ssB[2 * j + 1] * w1l + b1l) * dB[2 * j + 1];
                h1pA[j] = pk2(a0, a1);
                h1pB[j] = pk2(c0, c1);
            }
            h16A = elu_f(ssA[16] * w1l + b1l) * dA[16];
            h16B = elu_f(ssB[16] * w1l + b1l) * dB[16];
        }

        // agg[n] = dv[n] * ( sum_m A[n,m]*h1d[m] + h1d[n] )   (A and B)
        #pragma unroll
        for (int n = 0; n < NN; n++) {
            const ulonglong2* avA = reinterpret_cast<const ulonglong2*>(&curA[n * 20]);
            const ulonglong2* avB = reinterpret_cast<const ulonglong2*>(&curB[n * 20]);
            ull a0 = 0ull, a1 = 0ull, b0 = 0ull, b1v = 0ull;
            #pragma unroll
            for (int q = 0; q < 4; q++) {
                ulonglong2 vA = avA[q];
                ulonglong2 vB = avB[q];
                ffma2(a0,  vA.x, h1pA[2 * q]);
                ffma2(a1,  vA.y, h1pA[2 * q + 1]);
                ffma2(b0,  vB.x, h1pB[2 * q]);
                ffma2(b1v, vB.y, h1pB[2 * q + 1]);
            }
            float diagA = (n < 16) ? getp(h1pA, n) : h16A;
            float diagB = (n < 16) ? getp(h1pB, n) : h16B;
            float l0, h0, l1, h1;
            upk2(a0, l0, h0); upk2(a1, l1, h1);
            float accA = (l0 + h0) + (l1 + h1) + curA[n * 20 + 16] * h16A + diagA;
            upk2(b0, l0, h0); upk2(b1v, l1, h1);
            float accB = (l0 + h0) + (l1 + h1) + curB[n * 20 + 16] * h16B + diagB;
            bufA[n * 36 + lane] = accA * dA[n];
            bufB[n * 36 + lane] = accB * dB[n];
        }
        __syncwarp();

        // t = agg @ W2 + b2 ; h2 = elu(t) ; fp16 store  (A and B)
        __half* outA = gH2h + bA * (NN * H);
        __half* outB = gH2h + bB * (NN * H);
        #pragma unroll
        for (int n = 0; n < NN; n++) {
            const ulonglong2* bvA = reinterpret_cast<const ulonglong2*>(&bufA[n * 36]);
            const ulonglong2* bvB = reinterpret_cast<const ulonglong2*>(&bufB[n * 36]);
            ull a0 = 0ull, a1 = 0ull, b0 = 0ull, b1v = 0ull;
            #pragma unroll
            for (int q = 0; q < 8; q++) {
                ulonglong2 vA = bvA[q];
                ulonglong2 vB = bvB[q];
                ffma2(a0,  vA.x, W2p[2 * q]);
                ffma2(a1,  vA.y, W2p[2 * q + 1]);
                ffma2(b0,  vB.x, W2p[2 * q]);
                ffma2(b1v, vB.y, W2p[2 * q + 1]);
            }
            float l0, h0, l1, h1;
            upk2(a0, l0, h0); upk2(a1, l1, h1);
            outA[n * H + lane] = __float2half(elu_f((l0 + h0) + (l1 + h1) + b2l));
            upk2(b0, l0, h0); upk2(b1v, l1, h1);
            outB[n * H + lane] = __float2half(elu_f((l0 + h0) + (l1 + h1) + b2l));
        }
        __syncwarp();
    }
}

// ---------------------------------------------------------------------------
// Streaming BN-stats over gH2h. 272 threads: thread t owns half2 slot t of each
// sample (n = t/16). Coalesced warp reads; fp32 local accum then atomics.
__global__ __launch_bounds__(272) void stats_kernel() {
    __shared__ float sAcc[2 * NN];
    const int t = threadIdx.x;               // 0..271
    if (t < 2 * NN) sAcc[t] = 0.f;
    __syncthreads();

    const int n = t >> 4;
    const __half2* p = reinterpret_cast<const __half2*>(gH2h);
    float sum = 0.f, sq = 0.f;
    for (long b = blockIdx.x; b < B_TOT; b += gridDim.x) {
        float2 v = __half22float2(p[b * 272 + t]);
        sum += v.x + v.y;
        sq  += v.x * v.x + v.y * v.y;
    }
    atomicAdd(&sAcc[n], sum);
    atomicAdd(&sAcc[NN + n], sq);
    __syncthreads();
    if (t < NN)           atomicAdd(&gSum[t],      sAcc[t]);
    else if (t < 2 * NN)  atomicAdd(&gSq[t - NN],  sAcc[t]);
}

// ---------------------------------------------------------------------------
__global__ void finalize_kernel(const float* __restrict__ gamma,
                                const float* __restrict__ beta)
{
    int n = threadIdx.x;
    float Cl = 0.f;
    if (n < NN) {
        const float inv_cnt = 1.f / ((float)B_TOT * (float)H);
        float mean = gSum[n] * inv_cnt;
        float var  = gSq[n] * inv_cnt - mean * mean;
        float rs   = rsqrtf(var + EPS);
        float A    = gamma[n] * rs;
        float C    = beta[n] - mean * A;
        gA[n] = A * (1.f / 17.f);
        Cl    = C * (1.f / 17.f);
    }
    #pragma unroll
    for (int off = 16; off; off >>= 1) Cl += __shfl_xor_sync(0xffffffffu, Cl, off);
    if (n == 0) gCbar = Cl;
}

// ---------------------------------------------------------------------------
// Pass 2: BN-fold + node mean + MLP head (unchanged from R7).
#define P2_WARPS 4
#define GESTRIDE 33

__global__ __launch_bounds__(128) void pass2_kernel(
    const float* __restrict__ x_raw,   // [B,17]
    const float* __restrict__ x_cov,   // [B,3]
    const float* __restrict__ age,     // [B,1]
    const float* __restrict__ Wr1,     // [53,64]
    const float* __restrict__ br1,     // [64]
    const float* __restrict__ Wr2,     // [64,32]
    const float* __restrict__ br2,     // [32]
    const float* __restrict__ Wr3,     // [32,1]
    const float* __restrict__ br3,     // [1]
    float* __restrict__ out)           // [B,1]
{
    __shared__ __align__(16) float Wr1s[D_IN * 64];
    __shared__ __align__(16) float Wr2s[64 * H];
    __shared__ __align__(16) float geS[P2_WARPS][32 * GESTRIDE];
    __shared__ __align__(16) float br1s[64];
    __shared__ __align__(16) float br2s[H];
    __shared__ __align__(16) float wr3s[H];
    __shared__ float As_[NN + 1];
    __shared__ float misc[2];

    const int tid = threadIdx.x;
    for (int i = tid; i < D_IN * 64; i += 128) Wr1s[i] = Wr1[i];
    for (int i = tid; i < 64 * H;   i += 128) Wr2s[i] = Wr2[i];
    if (tid < 64) br1s[tid] = br1[tid];
    if (tid < 32) { br2s[tid] = br2[tid]; wr3s[tid] = Wr3[tid]; }
    if (tid < NN) As_[tid] = gA[tid];
    if (tid == 0) { misc[0] = gCbar; misc[1] = br3[0]; }
    __syncthreads();

    const int lane = tid & 31;
    const int w    = tid >> 5;
    float* ge = geS[w];
    const long base = ((long)blockIdx.x * P2_WARPS + w) * 32;

    float As_r[NN];
    #pragma unroll
    for (int n = 0; n < NN; n++) As_r[n] = As_[n];
    const float cbar = misc[0];

    // ---- Phase A: graph_emb (BN-folded) for this warp's 32 samples ----
    #pragma unroll 1
    for (int s2 = 0; s2 < 32; s2++) {
        const __half* hp = gH2h + (base + s2) * (NN * H);
        float g = cbar;
        #pragma unroll
        for (int n = 0; n < NN; n++)
            g += As_r[n] * __half2float(hp[n * H + lane]);
        ge[s2 * GESTRIDE + lane] = g;
    }
    __syncwarp();

    // ---- Phase B: lane = sample ----
    const long b = base + lane;
    const float* cl = ge + lane * GESTRIDE;

    float xr[21];
    {
        const float* xrp = x_raw + b * NN;
        #pragma unroll
        for (int i = 0; i < NN; i++) xr[i] = xrp[i];
        const float* xcp = x_cov + b * 3;
        xr[17] = xcp[0]; xr[18] = xcp[1]; xr[19] = xcp[2];
        xr[20] = age[b];
    }

    ull z2a[16];
    const ull* b2u = reinterpret_cast<const ull*>(br2s);
    #pragma unroll
    for (int j = 0; j < 16; j++) z2a[j] = b2u[j];

    #pragma unroll
    for (int c = 0; c < 4; c++) {
        ull za[8];
        const ull* b1u = reinterpret_cast<const ull*>(br1s + 16 * c);
        #pragma unroll
        for (int j = 0; j < 8; j++) za[j] = b1u[j];

        #pragma unroll 1
        for (int p = 0; p < 16; p++) {
            float f0 = cl[2 * p];
            float f1 = cl[2 * p + 1];
            ull ca = pk2(f0, f0);
            ull cb = pk2(f1, f1);
            const ulonglong2* wa = reinterpret_cast<const ulonglong2*>(&Wr1s[(2 * p) * 64 + 16 * c]);
            const ulonglong2* wb = reinterpret_cast<const ulonglong2*>(&Wr1s[(2 * p + 1) * 64 + 16 * c]);
            #pragma unroll
            for (int q = 0; q < 4; q++) {
                ulonglong2 va = wa[q];
                ffma2(za[2 * q],     ca, va.x);
                ffma2(za[2 * q + 1], ca, va.y);
            }
            #pragma unroll
            for (int q = 0; q < 4; q++) {
                ulonglong2 vb = wb[q];
                ffma2(za[2 * q],     cb, vb.x);
                ffma2(za[2 * q + 1], cb, vb.y);
            }
        }
        #pragma unroll 1
        for (int p = 0; p < 10; p++) {
            float f0 = xr[2 * p];
            float f1 = xr[2 * p + 1];
            ull ca = pk2(f0, f0);
            ull cb = pk2(f1, f1);
            const ulonglong2* wa = reinterpret_cast<const ulonglong2*>(&Wr1s[(32 + 2 * p) * 64 + 16 * c]);
            const ulonglong2* wb = reinterpret_cast<const ulonglong2*>(&Wr1s[(33 + 2 * p) * 64 + 16 * c]);
            #pragma unroll
            for (int q = 0; q < 4; q++) {
                ulonglong2 va = wa[q];
                ffma2(za[2 * q],     ca, va.x);
                ffma2(za[2 * q + 1], ca, va.y);
            }
            #pragma unroll
            for (int q = 0; q < 4; q++) {
                ulonglong2 vb = wb[q];
                ffma2(za[2 * q],     cb, vb.x);
                ffma2(za[2 * q + 1], cb, vb.y);
            }
        }
        {
            float ci = xr[20];
            ull c2 = pk2(ci, ci);
            const ulonglong2* wv = reinterpret_cast<const ulonglong2*>(&Wr1s[52 * 64 + 16 * c]);
            #pragma unroll
            for (int q = 0; q < 4; q++) {
                ulonglong2 v = wv[q];
                ffma2(za[2 * q],     c2, v.x);
                ffma2(za[2 * q + 1], c2, v.y);
            }
        }

        #pragma unroll
        for (int j = 0; j < 8; j++) {
            float r0, r1; upk2(za[j], r0, r1);
            r0 = fmaxf(r0, 0.f); r1 = fmaxf(r1, 0.f);
            int k0 = 16 * c + 2 * j;
            ull ca = pk2(r0, r0);
            ull cb = pk2(r1, r1);
            const ulonglong2* wa = reinterpret_cast<const ulonglong2*>(&Wr2s[k0 * 32]);
            const ulonglong2* wb = reinterpret_cast<const ulonglong2*>(&Wr2s[(k0 + 1) * 32]);
            #pragma unroll
            for (int q = 0; q < 8; q++) {
                ulonglong2 va = wa[q];
                ffma2(z2a[2 * q],     ca, va.x);
                ffma2(z2a[2 * q + 1], ca, va.y);
            }
            #pragma unroll
            for (int q = 0; q < 8; q++) {
                ulonglong2 vb = wb[q];
                ffma2(z2a[2 * q],     cb, vb.x);
                ffma2(z2a[2 * q + 1], cb, vb.y);
            }
        }
    }

    float acc = misc[1];
    #pragma unroll
    for (int j = 0; j < 16; j++) {
        float lo, hi; upk2(z2a[j], lo, hi);
        acc += fmaxf(lo, 0.f) * wr3s[2 * j];
        acc += fmaxf(hi, 0.f) * wr3s[2 * j + 1];
    }
    out[b] = 1.f / (1.f + __expf(-acc));
}

// ---------------------------------------------------------------------------
extern "C" void kernel_launch(void* const* d_in, const int* in_sizes, int n_in,
                              void* d_out, int out_size)
{
    const float* x_str = (const float*)d_in[0];
    const float* x_raw = (const float*)d_in[1];
    const float* adj   = (const float*)d_in[2];
    const float* x_cov = (const float*)d_in[3];
    const float* age   = (const float*)d_in[4];
    const float* W1    = (const float*)d_in[5];
    const float* b1    = (const float*)d_in[6];
    const float* W2    = (const float*)d_in[7];
    const float* b2    = (const float*)d_in[8];
    const float* gamma = (const float*)d_in[9];
    const float* beta  = (const float*)d_in[10];
    const float* Wr1   = (const float*)d_in[11];
    const float* br1   = (const float*)d_in[12];
    const float* Wr2   = (const float*)d_in[13];
    const float* br2   = (const float*)d_in[14];
    const float* Wr3   = (const float*)d_in[15];
    const float* br3   = (const float*)d_in[16];

    const int blocks1 = B_TOT / (WPB * SPW);          // 2048
    const int blocks2 = B_TOT / (P2_WARPS * 32);      // 1024
    const int smem1   = P1_FLOATS * 4;                // ~89 KB

    static int attr_done = 0;
    if (!attr_done) {
        cudaFuncSetAttribute(pass1_kernel,
                             cudaFuncAttributeMaxDynamicSharedMemorySize, smem1);
        attr_done = 1;
    }

    zero_stats_kernel<<<1, 32>>>();
    pass1_kernel<<<blocks1, 256, smem1>>>(x_str, adj, W1, b1, W2, b2);
    stats_kernel<<<2048, 272>>>();
    finalize_kernel<<<1, 32>>>(gamma, beta);
    pass2_kernel<<<blocks2, 128>>>(x_raw, x_cov, age,
                                   Wr1, br1, Wr2, br2, Wr3, br3,
                                   (float*)d_out);
}